// round 14
// baseline (speedup 1.0000x reference)
#include <cuda_runtime.h>
#include <cuda_bf16.h>
#include <cstdint>

// ---------------------------------------------------------------------------
// SemlaLayer: equi + inv attention, B=8, N=256, D_EQUI=64, H=16, D_HEAD=16
// Two-stream overlap: [null] prep_e -> equi_attn(fused out-proj)
//                     [s2]   init_i -> prep_i(splitK) -> inv_attn -> out_inv
// ---------------------------------------------------------------------------
#define Bsz 8
#define Nn  256
#define CEQ 64
#define DIN 256
#define L2E 1.4426950408889634f
#define KTE 16
#define KTI 16

typedef unsigned long long u64;

// Scratch (device globals; no allocation allowed)
__device__ __align__(128) float g_proj_e[Bsz * Nn * 3 * CEQ];
__device__ __align__(128) float g_proj_i[Bsz * Nn * DIN];
__device__ __align__(128) float g_out_i [Bsz * Nn * DIN];

__device__ __forceinline__ float ex2f(float x) {
    float r;
    asm("ex2.approx.ftz.f32 %0, %1;" : "=f"(r) : "f"(x));
    return r;
}
__device__ __forceinline__ u64 pack2(float lo, float hi) {
    u64 r;
    asm("mov.b64 %0, {%1, %2};" : "=l"(r) : "f"(lo), "f"(hi));
    return r;
}
__device__ __forceinline__ float2 unpack2(u64 v) {
    float2 f;
    asm("mov.b64 {%0, %1}, %2;" : "=f"(f.x), "=f"(f.y) : "l"(v));
    return f;
}
__device__ __forceinline__ void fma2(u64& d, u64 a, u64 b) {
    asm("fma.rn.f32x2 %0, %1, %2, %3;" : "=l"(d) : "l"(a), "l"(b), "l"(d));
}
__device__ __forceinline__ void add2(u64& d, u64 a) {
    asm("add.rn.f32x2 %0, %1, %2;" : "=l"(d) : "l"(a), "l"(d));
}

__device__ __forceinline__ void cp16(float* dst_smem, const float* src) {
    uint32_t d = (uint32_t)__cvta_generic_to_shared(dst_smem);
    asm volatile("cp.async.cg.shared.global [%0], [%1], 16;" :: "r"(d), "l"(src) : "memory");
}
__device__ __forceinline__ void cp_commit() {
    asm volatile("cp.async.commit_group;" ::: "memory");
}
template <int N> __device__ __forceinline__ void cp_wait() {
    asm volatile("cp.async.wait_group %0;" :: "n"(N) : "memory");
}

// ---------------------------------------------------------------------------
// f32x2 GEMM tile: C[m_base:+64, n_base:+64] += / = X[:, k0:k0+16*ksteps] @ W^T
// 256 threads, BK=16, double-buffered smem. ATOMIC: atomicAdd epilogue, no bias.
// ---------------------------------------------------------------------------
template <bool ATOMIC>
__device__ __forceinline__ void gemm_tile64(
    const float* __restrict__ X, const float* __restrict__ W,
    const float* __restrict__ bias, float* __restrict__ C,
    int Nout, int K, int m_base, int n_base, int k0, int ksteps, float* sm)
{
    const int t = threadIdx.x;
    const int tx = t & 15, ty = t >> 4;
    const int lm = t >> 2;
    const int lk = (t & 3) * 4;

    u64 acc[2][4];
#pragma unroll
    for (int i = 0; i < 2; i++)
#pragma unroll
        for (int j = 0; j < 4; j++) acc[i][j] = 0ull;

    {
        float4 vx = *(const float4*)&X[(size_t)(m_base + lm) * K + k0 + lk];
        float4 vw = *(const float4*)&W[(size_t)(n_base + lm) * K + k0 + lk];
        float* Xs = sm;
        float* Ws = sm + 1088;
        Xs[(lk + 0) * 68 + lm] = vx.x; Xs[(lk + 1) * 68 + lm] = vx.y;
        Xs[(lk + 2) * 68 + lm] = vx.z; Xs[(lk + 3) * 68 + lm] = vx.w;
        Ws[(lk + 0) * 68 + lm] = vw.x; Ws[(lk + 1) * 68 + lm] = vw.y;
        Ws[(lk + 2) * 68 + lm] = vw.z; Ws[(lk + 3) * 68 + lm] = vw.w;
    }
    __syncthreads();

    for (int s = 0; s < ksteps; s++) {
        float4 nx, nw;
        const bool more = (s + 1 < ksteps);
        if (more) {
            nx = *(const float4*)&X[(size_t)(m_base + lm) * K + k0 + (s + 1) * 16 + lk];
            nw = *(const float4*)&W[(size_t)(n_base + lm) * K + k0 + (s + 1) * 16 + lk];
        }
        const float* Xs = sm + (s & 1) * 2176;
        const float* Ws = Xs + 1088;
#pragma unroll
        for (int kk = 0; kk < 16; kk++) {
            const ulonglong2 ax = *(const ulonglong2*)&Xs[kk * 68 + ty * 4];
            const float4 bv = *(const float4*)&Ws[kk * 68 + tx * 4];
            const u64 b0 = pack2(bv.x, bv.x), b1 = pack2(bv.y, bv.y);
            const u64 b2 = pack2(bv.z, bv.z), b3 = pack2(bv.w, bv.w);
            fma2(acc[0][0], ax.x, b0); fma2(acc[0][1], ax.x, b1);
            fma2(acc[0][2], ax.x, b2); fma2(acc[0][3], ax.x, b3);
            fma2(acc[1][0], ax.y, b0); fma2(acc[1][1], ax.y, b1);
            fma2(acc[1][2], ax.y, b2); fma2(acc[1][3], ax.y, b3);
        }
        if (more) {
            float* Xd = sm + ((s + 1) & 1) * 2176;
            float* Wd = Xd + 1088;
            Xd[(lk + 0) * 68 + lm] = nx.x; Xd[(lk + 1) * 68 + lm] = nx.y;
            Xd[(lk + 2) * 68 + lm] = nx.z; Xd[(lk + 3) * 68 + lm] = nx.w;
            Wd[(lk + 0) * 68 + lm] = nw.x; Wd[(lk + 1) * 68 + lm] = nw.y;
            Wd[(lk + 2) * 68 + lm] = nw.z; Wd[(lk + 3) * 68 + lm] = nw.w;
        }
        __syncthreads();
    }

    if (ATOMIC) {
#pragma unroll
        for (int p = 0; p < 2; p++) {
            const int m = m_base + ty * 4 + p * 2;
#pragma unroll
            for (int j = 0; j < 4; j++) {
                const float2 f = unpack2(acc[p][j]);
                atomicAdd(&C[(size_t)m * Nout + n_base + tx * 4 + j], f.x);
                atomicAdd(&C[(size_t)(m + 1) * Nout + n_base + tx * 4 + j], f.y);
            }
        }
    } else {
        float4 bvec;
        if (bias) bvec = *(const float4*)&bias[n_base + tx * 4];
        else      bvec = make_float4(0.f, 0.f, 0.f, 0.f);
#pragma unroll
        for (int p = 0; p < 2; p++) {
            float4 lo, hi;
            float2 f;
            f = unpack2(acc[p][0]); lo.x = f.x + bvec.x; hi.x = f.y + bvec.x;
            f = unpack2(acc[p][1]); lo.y = f.x + bvec.y; hi.y = f.y + bvec.y;
            f = unpack2(acc[p][2]); lo.z = f.x + bvec.z; hi.z = f.y + bvec.z;
            f = unpack2(acc[p][3]); lo.w = f.x + bvec.w; hi.w = f.y + bvec.w;
            const int m = m_base + ty * 4 + p * 2;
            *(float4*)&C[(size_t)m * Nout + n_base + tx * 4] = lo;
            *(float4*)&C[(size_t)(m + 1) * Nout + n_base + tx * 4] = hi;
        }
    }
}

// ---------------------------------------------------------------------------
// prep_e: equi input GEMM (96 CTAs, serial-K).
// init_i: seed g_proj_i with bias.  prep_i: 4-way split-K (512 CTAs, atomic).
// ---------------------------------------------------------------------------
__global__ void __launch_bounds__(256) prep_e_kernel(
    const float* __restrict__ v_equi, const float* __restrict__ W_coord)
{
    __shared__ __align__(16) float sm[2 * 2 * 16 * 68];
    gemm_tile64<false>(v_equi, W_coord, nullptr, g_proj_e, CEQ, CEQ,
                       blockIdx.x * 64, 0, 0, CEQ / 16, sm);
}

__global__ void __launch_bounds__(256) init_i_kernel(const float* __restrict__ b_in) {
    const int idx = blockIdx.x * 256 + threadIdx.x;   // 131072 float4
    const int n4 = idx & 63;
    const float4 v = *(const float4*)&b_in[n4 * 4];
    *(float4*)&g_proj_i[(size_t)idx * 4] = v;
}

__global__ void __launch_bounds__(256) prep_i_kernel(
    const float* __restrict__ v_inv, const float* __restrict__ W_in)
{
    __shared__ __align__(16) float sm[2 * 2 * 16 * 68];
    const int bx = blockIdx.x;                  // 4 kslices x 128 tiles
    const int ks = bx >> 7;
    const int id = bx & 127;
    gemm_tile64<true>(v_inv, W_in, nullptr, g_proj_i, DIN, DIN,
                      (id >> 2) * 64, (id & 3) * 64, ks * 64, 4, sm);
}

// ---------------------------------------------------------------------------
// Equi attention, 512 CTAs x 128 threads, 3-stage cp.async pipeline,
// ONE __syncthreads per tile. Fused output projection writes d_out.
// smem: 3 tile buffers (9216 floats) + mask = 40.9 KB -> 5 CTAs/SM.
// ---------------------------------------------------------------------------
struct __align__(16) EquiSm {
    float proj[3 * KTE * 192];   // tail overlays rows + Wt here
    float mask[4 * 256];
};

__global__ void __launch_bounds__(128, 5) equi_attn_kernel(
    const float* __restrict__ em,      // [B,N,N,64]
    const int*   __restrict__ adj,     // [B,N,N]
    const float* __restrict__ W_eo,    // [64,64]
    const float* __restrict__ b_eo,    // [64]
    float* __restrict__ out_equi)      // d_out equi part [B,N,3,64]
{
    __shared__ EquiSm sm;
    const int bx = blockIdx.x;
    const int t = threadIdx.x;
    const int wid = t >> 5, lane = t & 31;
    const int c4 = lane & 15;
    const int ksub = lane >> 4;
    const int qg = bx & 63, b = bx >> 6;
    const int q = qg * 4 + wid;

    // mask from adj: warp computes its q-row
    {
        const int* arow = adj + (size_t)(b * Nn + q) * Nn;
        const int4 a0 = *(const int4*)&arow[lane * 8];
        const int4 a1 = *(const int4*)&arow[lane * 8 + 4];
        const bool c0 = a0.x != 0, c1 = a0.y != 0, c2 = a0.z != 0, c3 = a0.w != 0;
        const bool c5 = a1.x != 0, c6 = a1.y != 0, c7 = a1.z != 0, c8 = a1.w != 0;
        const unsigned any = __ballot_sync(0xffffffffu,
            c0 | c1 | c2 | c3 | c5 | c6 | c7 | c8);
        const float neg = any ? -1e30f : 0.0f;
        float4 m0, m1;
        m0.x = c0 ? 0.0f : neg; m0.y = c1 ? 0.0f : neg;
        m0.z = c2 ? 0.0f : neg; m0.w = c3 ? 0.0f : neg;
        m1.x = c5 ? 0.0f : neg; m1.y = c6 ? 0.0f : neg;
        m1.z = c7 ? 0.0f : neg; m1.w = c8 ? 0.0f : neg;
        *(float4*)&sm.mask[wid * 256 + lane * 8] = m0;
        *(float4*)&sm.mask[wid * 256 + lane * 8 + 4] = m1;
    }
    // prefetch tiles 0 and 1 (one commit group each)
#pragma unroll
    for (int pre = 0; pre < 2; pre++) {
#pragma unroll
        for (int r = 0; r < 6; r++) {
            const int j = t + r * 128;
            const int k = j / 48, rem = j % 48;
            const int d = rem >> 4, cl = (rem & 15) * 4;
            cp16(&sm.proj[pre * 3072 + k * 192 + d * 64 + cl],
                 &g_proj_e[((size_t)(b * Nn + pre * KTE + k) * 3 + d) * CEQ + cl]);
        }
        cp_commit();
    }

    u64 S2[2], Q2[2], D2[6];
#pragma unroll
    for (int j = 0; j < 2; j++) { S2[j] = 0ull; Q2[j] = 0ull; }
#pragma unroll
    for (int r = 0; r < 6; r++) D2[r] = 0ull;

    const float* emq = em + (size_t)(b * Nn + q) * (Nn * CEQ);
    const float* mq = sm.mask + wid * 256;

    const int NT = Nn / KTE;   // 16
#pragma unroll 1
    for (int ti = 0; ti < NT; ti++) {
        if (ti + 1 < NT) cp_wait<1>(); else cp_wait<0>();
        __syncthreads();
        if (ti + 2 < NT) {
            const int kb2 = (ti + 2) * KTE;
            float* dst = sm.proj + ((ti + 2) % 3) * 3072;
#pragma unroll
            for (int r = 0; r < 6; r++) {
                const int j = t + r * 128;
                const int k = j / 48, rem = j % 48;
                const int d = rem >> 4, cl = (rem & 15) * 4;
                cp16(&dst[k * 192 + d * 64 + cl],
                     &g_proj_e[((size_t)(b * Nn + kb2 + k) * 3 + d) * CEQ + cl]);
            }
            cp_commit();
        }
        const float* ps = sm.proj + (ti % 3) * 3072;
        const int kb = ti * KTE;
#pragma unroll
        for (int it = 0; it < KTE / 2; it++) {
            const int kl = it * 2 + ksub;
            const int k = kb + kl;
            const float4 x = *(const float4*)&emq[(size_t)k * CEQ + c4 * 4];
            const float mk = mq[k];
            const float a0 = ex2f(fmaf(x.x, L2E, mk));
            const float a1 = ex2f(fmaf(x.y, L2E, mk));
            const float a2 = ex2f(fmaf(x.z, L2E, mk));
            const float a3 = ex2f(fmaf(x.w, L2E, mk));
            const u64 pA = pack2(a0, a1), pB = pack2(a2, a3);
            add2(S2[0], pA);      add2(S2[1], pB);
            fma2(Q2[0], pA, pA);  fma2(Q2[1], pB, pB);
            const ulonglong2 va = *(const ulonglong2*)&ps[kl * 192 +   0 + c4 * 4];
            const ulonglong2 vb = *(const ulonglong2*)&ps[kl * 192 +  64 + c4 * 4];
            const ulonglong2 vc = *(const ulonglong2*)&ps[kl * 192 + 128 + c4 * 4];
            fma2(D2[0], pA, va.x); fma2(D2[1], pB, va.y);
            fma2(D2[2], pA, vb.x); fma2(D2[3], pB, vb.y);
            fma2(D2[4], pA, vc.x); fma2(D2[5], pB, vc.y);
        }
    }
    __syncthreads();   // all warps done reading tile buffers before overlay

    // reduce across the 2 ksub lanes
    {
#pragma unroll
        for (int j = 0; j < 2; j++) {
            u64 v;
            v = __shfl_xor_sync(0xffffffffu, S2[j], 16); add2(S2[j], v);
            v = __shfl_xor_sync(0xffffffffu, Q2[j], 16); add2(Q2[j], v);
        }
#pragma unroll
        for (int r = 0; r < 6; r++) {
            u64 v;
            v = __shfl_xor_sync(0xffffffffu, D2[r], 16); add2(D2[r], v);
        }
    }

    // scaled rows -> smem rows area [12][68] at proj[0..816)
    if (ksub == 0) {
        const float2 sA = unpack2(S2[0]), sB = unpack2(S2[1]);
        const float2 qA = unpack2(Q2[0]), qB = unpack2(Q2[1]);
        const float Sv[4] = {sA.x, sA.y, sB.x, sB.y};
        const float Qv[4] = {qA.x, qA.y, qB.x, qB.y};
        float sc[4];
#pragma unroll
        for (int j = 0; j < 4; j++) {
            const float iv = 1.0f / Sv[j];
            sc[j] = sqrtf(Qv[j]) * iv * iv;
        }
#pragma unroll
        for (int d = 0; d < 3; d++) {
            const float2 dA = unpack2(D2[d * 2]), dB = unpack2(D2[d * 2 + 1]);
            float4 o;
            o.x = dA.x * sc[0]; o.y = dA.y * sc[1];
            o.z = dB.x * sc[2]; o.w = dB.y * sc[3];
            *(float4*)&sm.proj[(wid * 3 + d) * 68 + c4 * 4] = o;
        }
    }

    // load W_eo transposed into smem at proj[1024..5376): Wt[c][o], stride 68
    float* Wt = sm.proj + 1024;
#pragma unroll
    for (int r = 0; r < 8; r++) {
        const int j = t + r * 128;        // 1024 float4
        const int o = j >> 4, cq = (j & 15) * 4;
        const float4 w = *(const float4*)&W_eo[o * 64 + cq];
        Wt[(cq + 0) * 68 + o] = w.x;
        Wt[(cq + 1) * 68 + o] = w.y;
        Wt[(cq + 2) * 68 + o] = w.z;
        Wt[(cq + 3) * 68 + o] = w.w;
    }
    __syncthreads();

    // in-CTA output projection: warp handles rows [wid*3, wid*3+3);
    // lane covers outputs o = lane*2, lane*2+1
    const u64 bias2 = *(const u64*)&b_eo[lane * 2];
#pragma unroll
    for (int d = 0; d < 3; d++) {
        const int r = wid * 3 + d;
        u64 acc = 0ull;
#pragma unroll
        for (int cq = 0; cq < 16; cq++) {
            const float4 rv = *(const float4*)&sm.proj[r * 68 + cq * 4];
            fma2(acc, pack2(rv.x, rv.x), *(const u64*)&Wt[(cq * 4 + 0) * 68 + lane * 2]);
            fma2(acc, pack2(rv.y, rv.y), *(const u64*)&Wt[(cq * 4 + 1) * 68 + lane * 2]);
            fma2(acc, pack2(rv.z, rv.z), *(const u64*)&Wt[(cq * 4 + 2) * 68 + lane * 2]);
            fma2(acc, pack2(rv.w, rv.w), *(const u64*)&Wt[(cq * 4 + 3) * 68 + lane * 2]);
        }
        add2(acc, bias2);
        const float2 ov = unpack2(acc);
        float* op = out_equi + (((size_t)(b * Nn + q) * 3 + d) * CEQ);
        *(float2*)&op[lane * 2] = ov;
    }
}

// ---------------------------------------------------------------------------
// Inv attention, 512 CTAs x 128 threads, 3-stage pipeline, 1 sync/tile.
// smem: 3 x 2080 + mask = 33 KB -> 6 CTAs/SM.
// ---------------------------------------------------------------------------
struct __align__(16) InvSm {
    float hf[3][8 * 260];
    float mask[8 * 256];
};

__global__ void __launch_bounds__(128, 6) inv_attn_kernel(
    const float* __restrict__ im,      // [B,N,N,16]
    const int*   __restrict__ adj)     // [B,N,N]
{
    __shared__ InvSm sm;
    const int id = blockIdx.x;
    const int t = threadIdx.x;
    const int wid = t >> 5, lane = t & 31;
    const int hg = id & 1, qg = (id >> 1) & 31, b = id >> 6;
    const int h = lane & 7;
    const int ksub = lane >> 3;
    const int hbase = hg * 8;
    const int q0 = qg * 8 + wid * 2;

#pragma unroll
    for (int j = 0; j < 2; j++) {
        const int* arow = adj + (size_t)(b * Nn + q0 + j) * Nn;
        const int4 a0 = *(const int4*)&arow[lane * 8];
        const int4 a1 = *(const int4*)&arow[lane * 8 + 4];
        const bool c0 = a0.x != 0, c1 = a0.y != 0, c2 = a0.z != 0, c3 = a0.w != 0;
        const bool c5 = a1.x != 0, c6 = a1.y != 0, c7 = a1.z != 0, c8 = a1.w != 0;
        const unsigned any = __ballot_sync(0xffffffffu,
            c0 | c1 | c2 | c3 | c5 | c6 | c7 | c8);
        const float neg = any ? -1e30f : 0.0f;
        float4 m0, m1;
        m0.x = c0 ? 0.0f : neg; m0.y = c1 ? 0.0f : neg;
        m0.z = c2 ? 0.0f : neg; m0.w = c3 ? 0.0f : neg;
        m1.x = c5 ? 0.0f : neg; m1.y = c6 ? 0.0f : neg;
        m1.z = c7 ? 0.0f : neg; m1.w = c8 ? 0.0f : neg;
        *(float4*)&sm.mask[(wid * 2 + j) * 256 + lane * 8] = m0;
        *(float4*)&sm.mask[(wid * 2 + j) * 256 + lane * 8 + 4] = m1;
    }
    // prefetch tiles 0, 1
#pragma unroll
    for (int pre = 0; pre < 2; pre++) {
#pragma unroll
        for (int r = 0; r < 4; r++) {
            const int j = t + r * 128;
            const int k = j >> 5, rem = j & 31;
            const int hh = rem >> 2, e4 = (rem & 3) * 4;
            cp16(&sm.hf[pre][hh * 260 + k * 16 + e4],
                 &g_proj_i[(size_t)(b * Nn + pre * KTI + k) * DIN + (hbase + hh) * 16 + e4]);
        }
        cp_commit();
    }

    float S0 = 0.0f, SQ0 = 0.0f, S1 = 0.0f, SQ1 = 0.0f;
    u64 Aa[8], Ab[8];
#pragma unroll
    for (int e = 0; e < 8; e++) { Aa[e] = 0ull; Ab[e] = 0ull; }

    const float* imq0 = im + (size_t)(b * Nn + q0) * (Nn * 16) + hbase + h;
    const float* imq1 = imq0 + Nn * 16;
    const float* mq0 = sm.mask + (wid * 2) * 256;
    const float* mq1 = mq0 + 256;

    const int NT = Nn / KTI;   // 16
#pragma unroll 1
    for (int ti = 0; ti < NT; ti++) {
        if (ti + 1 < NT) cp_wait<1>(); else cp_wait<0>();
        __syncthreads();
        if (ti + 2 < NT) {
            const int kb2 = (ti + 2) * KTI;
            float* dst = sm.hf[(ti + 2) % 3];
#pragma unroll
            for (int r = 0; r < 4; r++) {
                const int j = t + r * 128;
                const int k = j >> 5, rem = j & 31;
                const int hh = rem >> 2, e4 = (rem & 3) * 4;
                cp16(&dst[hh * 260 + k * 16 + e4],
                     &g_proj_i[(size_t)(b * Nn + kb2 + k) * DIN + (hbase + hh) * 16 + e4]);
            }
            cp_commit();
        }
        const float* hs = sm.hf[ti % 3];
        const int kb = ti * KTI;
#pragma unroll
        for (int it = 0; it < KTI / 4; it++) {
            const int kl = it * 4 + ksub;
            const int k = kb + kl;
            const float x0 = imq0[(size_t)k * 16];
            const float x1 = imq1[(size_t)k * 16];
            const float p0 = ex2f(fmaf(x0, L2E, mq0[k]));
            const float p1 = ex2f(fmaf(x1, L2E, mq1[k]));
            S0 += p0; SQ0 = fmaf(p0, p0, SQ0);
            S1 += p1; SQ1 = fmaf(p1, p1, SQ1);
            const u64 pp0 = pack2(p0, p0);
            const u64 pp1 = pack2(p1, p1);
            const float* hk = hs + h * 260 + kl * 16;
            const ulonglong2 v0 = *(const ulonglong2*)&hk[0];
            const ulonglong2 v1 = *(const ulonglong2*)&hk[4];
            const ulonglong2 v2 = *(const ulonglong2*)&hk[8];
            const ulonglong2 v3 = *(const ulonglong2*)&hk[12];
            fma2(Aa[0], pp0, v0.x); fma2(Aa[1], pp0, v0.y);
            fma2(Aa[2], pp0, v1.x); fma2(Aa[3], pp0, v1.y);
            fma2(Aa[4], pp0, v2.x); fma2(Aa[5], pp0, v2.y);
            fma2(Aa[6], pp0, v3.x); fma2(Aa[7], pp0, v3.y);
            fma2(Ab[0], pp1, v0.x); fma2(Ab[1], pp1, v0.y);
            fma2(Ab[2], pp1, v1.x); fma2(Ab[3], pp1, v1.y);
            fma2(Ab[4], pp1, v2.x); fma2(Ab[5], pp1, v2.y);
            fma2(Ab[6], pp1, v3.x); fma2(Ab[7], pp1, v3.y);
        }
    }

#pragma unroll
    for (int m = 8; m <= 16; m <<= 1) {
        S0  += __shfl_xor_sync(0xffffffffu, S0,  m);
        SQ0 += __shfl_xor_sync(0xffffffffu, SQ0, m);
        S1  += __shfl_xor_sync(0xffffffffu, S1,  m);
        SQ1 += __shfl_xor_sync(0xffffffffu, SQ1, m);
#pragma unroll
        for (int e = 0; e < 8; e++) {
            u64 v;
            v = __shfl_xor_sync(0xffffffffu, Aa[e], m); add2(Aa[e], v);
            v = __shfl_xor_sync(0xffffffffu, Ab[e], m); add2(Ab[e], v);
        }
    }

    if (ksub == 0) {
        const float i0 = 1.0f / S0, i1 = 1.0f / S1;
        const float sc0 = sqrtf(SQ0) * i0 * i0;
        const float sc1 = sqrtf(SQ1) * i1 * i1;
        float* o0 = g_out_i + (size_t)(b * Nn + q0) * DIN + (hbase + h) * 16;
        float* o1 = o0 + DIN;
#pragma unroll
        for (int e4 = 0; e4 < 4; e4++) {
            const float2 lo0 = unpack2(Aa[e4 * 2]);
            const float2 hi0 = unpack2(Aa[e4 * 2 + 1]);
            const float2 lo1 = unpack2(Ab[e4 * 2]);
            const float2 hi1 = unpack2(Ab[e4 * 2 + 1]);
            float4 v0, v1;
            v0.x = lo0.x * sc0; v0.y = lo0.y * sc0;
            v0.z = hi0.x * sc0; v0.w = hi0.y * sc0;
            v1.x = lo1.x * sc1; v1.y = lo1.y * sc1;
            v1.z = hi1.x * sc1; v1.w = hi1.y * sc1;
            *(float4*)&o0[e4 * 4] = v0;
            *(float4*)&o1[e4 * 4] = v1;
        }
    }
}

// ---------------------------------------------------------------------------
// Output kernel (inv only): 128 CTAs, 32 m-tiles x 4 n-tiles
// ---------------------------------------------------------------------------
__global__ void __launch_bounds__(256) out_kernel(
    const float* __restrict__ W_out, const float* __restrict__ b_out,
    float* __restrict__ out)
{
    __shared__ __align__(16) float sm[2 * 2 * 16 * 68];
    const int id = blockIdx.x;
    gemm_tile64<false>(g_out_i, W_out, b_out, out + (size_t)Bsz * Nn * 3 * CEQ,
                       DIN, DIN, (id >> 2) * 64, (id & 3) * 64, 0, DIN / 16, sm);
}

// ---------------------------------------------------------------------------
// Launch: two-stream fork/join (graph-capturable pattern).
// ---------------------------------------------------------------------------
extern "C" void kernel_launch(void* const* d_in, const int* in_sizes, int n_in,
                              void* d_out, int out_size) {
    const float* v_equi     = (const float*)d_in[0];
    const float* v_inv      = (const float*)d_in[1];
    const float* em         = (const float*)d_in[2];
    const float* im         = (const float*)d_in[3];
    const int*   adj        = (const int*)  d_in[4];
    const float* W_coord    = (const float*)d_in[5];
    const float* W_equi_out = (const float*)d_in[6];
    const float* b_equi_out = (const float*)d_in[7];
    const float* W_in       = (const float*)d_in[8];
    const float* b_in       = (const float*)d_in[9];
    const float* W_out      = (const float*)d_in[10];
    const float* b_out      = (const float*)d_in[11];
    float* out = (float*)d_out;

    static cudaStream_t s2 = nullptr;
    static cudaEvent_t ev_fork = nullptr, ev_join = nullptr;
    if (s2 == nullptr) {
        cudaStreamCreateWithFlags(&s2, cudaStreamNonBlocking);
        cudaEventCreateWithFlags(&ev_fork, cudaEventDisableTiming);
        cudaEventCreateWithFlags(&ev_join, cudaEventDisableTiming);
    }

    // fork: s2 branches off the (capture) null stream
    cudaEventRecord(ev_fork, 0);
    cudaStreamWaitEvent(s2, ev_fork, 0);

    // stream B: inv chain
    init_i_kernel<<<512, 256, 0, s2>>>(b_in);
    prep_i_kernel<<<512, 256, 0, s2>>>(v_inv, W_in);
    inv_attn_kernel<<<512, 128, 0, s2>>>(im, adj);
    out_kernel<<<128, 256, 0, s2>>>(W_out, b_out, out);
    cudaEventRecord(ev_join, s2);

    // stream A (null): equi chain
    prep_e_kernel<<<96, 256>>>(v_equi, W_coord);
    equi_attn_kernel<<<512, 128>>>(em, adj, W_equi_out, b_equi_out, out);

    // join
    cudaStreamWaitEvent(0, ev_join, 0);
}

// round 15
// speedup vs baseline: 1.3016x; 1.3016x over previous
#include <cuda_runtime.h>
#include <cuda_bf16.h>
#include <cstdint>

// ---------------------------------------------------------------------------
// SemlaLayer: equi + inv attention, B=8, N=256, D_EQUI=64, H=16, D_HEAD=16
// Two-stream overlap: [null] prep_e -> equi_attn(em via cp.async, fused out)
//                     [s2]   prep_i -> inv_attn -> out_inv
// ---------------------------------------------------------------------------
#define Bsz 8
#define Nn  256
#define CEQ 64
#define DIN 256
#define L2E 1.4426950408889634f
#define KTE 16
#define KTI 16

typedef unsigned long long u64;

// Scratch (device globals; no allocation allowed)
__device__ __align__(128) float g_proj_e[Bsz * Nn * 3 * CEQ];
__device__ __align__(128) float g_proj_i[Bsz * Nn * DIN];
__device__ __align__(128) float g_out_i [Bsz * Nn * DIN];

__device__ __forceinline__ float ex2f(float x) {
    float r;
    asm("ex2.approx.ftz.f32 %0, %1;" : "=f"(r) : "f"(x));
    return r;
}
__device__ __forceinline__ u64 pack2(float lo, float hi) {
    u64 r;
    asm("mov.b64 %0, {%1, %2};" : "=l"(r) : "f"(lo), "f"(hi));
    return r;
}
__device__ __forceinline__ float2 unpack2(u64 v) {
    float2 f;
    asm("mov.b64 {%0, %1}, %2;" : "=f"(f.x), "=f"(f.y) : "l"(v));
    return f;
}
__device__ __forceinline__ void fma2(u64& d, u64 a, u64 b) {
    asm("fma.rn.f32x2 %0, %1, %2, %3;" : "=l"(d) : "l"(a), "l"(b), "l"(d));
}
__device__ __forceinline__ void add2(u64& d, u64 a) {
    asm("add.rn.f32x2 %0, %1, %2;" : "=l"(d) : "l"(a), "l"(d));
}

__device__ __forceinline__ void cp16(float* dst_smem, const float* src) {
    uint32_t d = (uint32_t)__cvta_generic_to_shared(dst_smem);
    asm volatile("cp.async.cg.shared.global [%0], [%1], 16;" :: "r"(d), "l"(src) : "memory");
}
__device__ __forceinline__ void cp_commit() {
    asm volatile("cp.async.commit_group;" ::: "memory");
}
template <int N> __device__ __forceinline__ void cp_wait() {
    asm volatile("cp.async.wait_group %0;" :: "n"(N) : "memory");
}

// ---------------------------------------------------------------------------
// f32x2 GEMM tile: C[m_base:+64, n_base:+64] = X @ W^T (+bias)
// 256 threads, BK=16, double-buffered smem, packed row-pair accumulators.
// ---------------------------------------------------------------------------
__device__ __forceinline__ void gemm_tile64(
    const float* __restrict__ X, const float* __restrict__ W,
    const float* __restrict__ bias, float* __restrict__ C,
    int Nout, int K, int m_base, int n_base, float* sm)
{
    const int t = threadIdx.x;
    const int tx = t & 15, ty = t >> 4;
    const int lm = t >> 2;
    const int lk = (t & 3) * 4;

    u64 acc[2][4];
#pragma unroll
    for (int i = 0; i < 2; i++)
#pragma unroll
        for (int j = 0; j < 4; j++) acc[i][j] = 0ull;

    {
        float4 vx = *(const float4*)&X[(size_t)(m_base + lm) * K + lk];
        float4 vw = *(const float4*)&W[(size_t)(n_base + lm) * K + lk];
        float* Xs = sm;
        float* Ws = sm + 1088;
        Xs[(lk + 0) * 68 + lm] = vx.x; Xs[(lk + 1) * 68 + lm] = vx.y;
        Xs[(lk + 2) * 68 + lm] = vx.z; Xs[(lk + 3) * 68 + lm] = vx.w;
        Ws[(lk + 0) * 68 + lm] = vw.x; Ws[(lk + 1) * 68 + lm] = vw.y;
        Ws[(lk + 2) * 68 + lm] = vw.z; Ws[(lk + 3) * 68 + lm] = vw.w;
    }
    __syncthreads();

    const int nsteps = K / 16;
    for (int s = 0; s < nsteps; s++) {
        float4 nx, nw;
        const bool more = (s + 1 < nsteps);
        if (more) {
            nx = *(const float4*)&X[(size_t)(m_base + lm) * K + (s + 1) * 16 + lk];
            nw = *(const float4*)&W[(size_t)(n_base + lm) * K + (s + 1) * 16 + lk];
        }
        const float* Xs = sm + (s & 1) * 2176;
        const float* Ws = Xs + 1088;
#pragma unroll
        for (int kk = 0; kk < 16; kk++) {
            const ulonglong2 ax = *(const ulonglong2*)&Xs[kk * 68 + ty * 4];
            const float4 bv = *(const float4*)&Ws[kk * 68 + tx * 4];
            const u64 b0 = pack2(bv.x, bv.x), b1 = pack2(bv.y, bv.y);
            const u64 b2 = pack2(bv.z, bv.z), b3 = pack2(bv.w, bv.w);
            fma2(acc[0][0], ax.x, b0); fma2(acc[0][1], ax.x, b1);
            fma2(acc[0][2], ax.x, b2); fma2(acc[0][3], ax.x, b3);
            fma2(acc[1][0], ax.y, b0); fma2(acc[1][1], ax.y, b1);
            fma2(acc[1][2], ax.y, b2); fma2(acc[1][3], ax.y, b3);
        }
        if (more) {
            float* Xd = sm + ((s + 1) & 1) * 2176;
            float* Wd = Xd + 1088;
            Xd[(lk + 0) * 68 + lm] = nx.x; Xd[(lk + 1) * 68 + lm] = nx.y;
            Xd[(lk + 2) * 68 + lm] = nx.z; Xd[(lk + 3) * 68 + lm] = nx.w;
            Wd[(lk + 0) * 68 + lm] = nw.x; Wd[(lk + 1) * 68 + lm] = nw.y;
            Wd[(lk + 2) * 68 + lm] = nw.z; Wd[(lk + 3) * 68 + lm] = nw.w;
        }
        __syncthreads();
    }

    float4 bvec;
    if (bias) bvec = *(const float4*)&bias[n_base + tx * 4];
    else      bvec = make_float4(0.f, 0.f, 0.f, 0.f);
#pragma unroll
    for (int p = 0; p < 2; p++) {
        float4 lo, hi;
        float2 f;
        f = unpack2(acc[p][0]); lo.x = f.x + bvec.x; hi.x = f.y + bvec.x;
        f = unpack2(acc[p][1]); lo.y = f.x + bvec.y; hi.y = f.y + bvec.y;
        f = unpack2(acc[p][2]); lo.z = f.x + bvec.z; hi.z = f.y + bvec.z;
        f = unpack2(acc[p][3]); lo.w = f.x + bvec.w; hi.w = f.y + bvec.w;
        const int m = m_base + ty * 4 + p * 2;
        *(float4*)&C[(size_t)m * Nout + n_base + tx * 4] = lo;
        *(float4*)&C[(size_t)(m + 1) * Nout + n_base + tx * 4] = hi;
    }
}

// ---------------------------------------------------------------------------
// prep_e: equi input GEMM (96 CTAs).   prep_i: inv input GEMM (128 CTAs).
// ---------------------------------------------------------------------------
__global__ void __launch_bounds__(256) prep_e_kernel(
    const float* __restrict__ v_equi, const float* __restrict__ W_coord)
{
    __shared__ __align__(16) float sm[2 * 2 * 16 * 68];
    gemm_tile64(v_equi, W_coord, nullptr, g_proj_e, CEQ, CEQ, blockIdx.x * 64, 0, sm);
}

__global__ void __launch_bounds__(256) prep_i_kernel(
    const float* __restrict__ v_inv,
    const float* __restrict__ W_in, const float* __restrict__ b_in)
{
    __shared__ __align__(16) float sm[2 * 2 * 16 * 68];
    const int id = blockIdx.x;                  // 32 m-tiles x 4 n-tiles
    gemm_tile64(v_inv, W_in, b_in, g_proj_i, DIN, DIN, (id >> 2) * 64, (id & 3) * 64, sm);
}

// ---------------------------------------------------------------------------
// Equi attention, 512 CTAs x 128 threads. Warp owns ONE q (4 q / CTA).
// em STREAMED THROUGH SMEM via cp.async (2-stage: em 16KB + proj 12KB per
// stage, 60KB total -> 3 CTAs/SM, ~84KB in flight per SM >> 17KB needed).
// Fused output projection writes d_out directly.
// ---------------------------------------------------------------------------
struct __align__(16) EquiSm {
    float em[2][4096];     // [q][k][ch] : q*1024 + k*64 + c ; overlay rows/Wt after
    float proj[2][3072];   // [k][d*64 + c]
    float mask[4 * 256];
};

__global__ void __launch_bounds__(128, 3) equi_attn_kernel(
    const float* __restrict__ em,      // [B,N,N,64]
    const int*   __restrict__ adj,     // [B,N,N]
    const float* __restrict__ W_eo,    // [64,64]
    const float* __restrict__ b_eo,    // [64]
    float* __restrict__ out_equi)      // d_out equi part [B,N,3,64]
{
    __shared__ EquiSm sm;
    const int bx = blockIdx.x;
    const int t = threadIdx.x;
    const int wid = t >> 5, lane = t & 31;
    const int c4 = lane & 15;
    const int ksub = lane >> 4;
    const int qg = bx & 63, b = bx >> 6;
    const int q = qg * 4 + wid;

    // mask from adj: warp computes its q-row
    {
        const int* arow = adj + (size_t)(b * Nn + q) * Nn;
        const int4 a0 = *(const int4*)&arow[lane * 8];
        const int4 a1 = *(const int4*)&arow[lane * 8 + 4];
        const bool c0 = a0.x != 0, c1 = a0.y != 0, c2 = a0.z != 0, c3 = a0.w != 0;
        const bool c5 = a1.x != 0, c6 = a1.y != 0, c7 = a1.z != 0, c8 = a1.w != 0;
        const unsigned any = __ballot_sync(0xffffffffu,
            c0 | c1 | c2 | c3 | c5 | c6 | c7 | c8);
        const float neg = any ? -1e30f : 0.0f;
        float4 m0, m1;
        m0.x = c0 ? 0.0f : neg; m0.y = c1 ? 0.0f : neg;
        m0.z = c2 ? 0.0f : neg; m0.w = c3 ? 0.0f : neg;
        m1.x = c5 ? 0.0f : neg; m1.y = c6 ? 0.0f : neg;
        m1.z = c7 ? 0.0f : neg; m1.w = c8 ? 0.0f : neg;
        *(float4*)&sm.mask[wid * 256 + lane * 8] = m0;
        *(float4*)&sm.mask[wid * 256 + lane * 8 + 4] = m1;
    }

    const size_t em_base = (size_t)(b * Nn + qg * 4) * (Nn * CEQ);

    // prefetch stages 0,1: em tile (1024 f4, 8/thread) + proj tile (768 f4, 6/thread)
#pragma unroll
    for (int pre = 0; pre < 2; pre++) {
#pragma unroll
        for (int r = 0; r < 8; r++) {
            const int j = t + r * 128;
            const int qq = j >> 8, rem = j & 255;
            const int k = rem >> 4, cl = (rem & 15) * 4;
            cp16(&sm.em[pre][qq * 1024 + k * 64 + cl],
                 &em[em_base + (size_t)qq * (Nn * CEQ) + (pre * KTE + k) * CEQ + cl]);
        }
#pragma unroll
        for (int r = 0; r < 6; r++) {
            const int j = t + r * 128;
            const int k = j / 48, rem = j % 48;
            const int d = rem >> 4, cl = (rem & 15) * 4;
            cp16(&sm.proj[pre][k * 192 + d * 64 + cl],
                 &g_proj_e[((size_t)(b * Nn + pre * KTE + k) * 3 + d) * CEQ + cl]);
        }
        cp_commit();
    }

    u64 S2[2], Q2[2], D2[6];
#pragma unroll
    for (int j = 0; j < 2; j++) { S2[j] = 0ull; Q2[j] = 0ull; }
#pragma unroll
    for (int r = 0; r < 6; r++) D2[r] = 0ull;

    const float* mq = sm.mask + wid * 256;

    const int NT = Nn / KTE;   // 16
#pragma unroll 1
    for (int ti = 0; ti < NT; ti++) {
        if (ti + 1 < NT) cp_wait<1>(); else cp_wait<0>();
        __syncthreads();
        const int buf = ti & 1;
        const float* emL = sm.em[buf] + wid * 1024;
        const float* ps = sm.proj[buf];
        const int kb = ti * KTE;
#pragma unroll
        for (int it = 0; it < KTE / 2; it++) {
            const int kl = it * 2 + ksub;
            const int k = kb + kl;
            const float4 x = *(const float4*)&emL[kl * 64 + c4 * 4];
            const float mk = mq[k];
            const float a0 = ex2f(fmaf(x.x, L2E, mk));
            const float a1 = ex2f(fmaf(x.y, L2E, mk));
            const float a2 = ex2f(fmaf(x.z, L2E, mk));
            const float a3 = ex2f(fmaf(x.w, L2E, mk));
            const u64 pA = pack2(a0, a1), pB = pack2(a2, a3);
            add2(S2[0], pA);      add2(S2[1], pB);
            fma2(Q2[0], pA, pA);  fma2(Q2[1], pB, pB);
            const ulonglong2 va = *(const ulonglong2*)&ps[kl * 192 +   0 + c4 * 4];
            const ulonglong2 vb = *(const ulonglong2*)&ps[kl * 192 +  64 + c4 * 4];
            const ulonglong2 vc = *(const ulonglong2*)&ps[kl * 192 + 128 + c4 * 4];
            fma2(D2[0], pA, va.x); fma2(D2[1], pB, va.y);
            fma2(D2[2], pA, vb.x); fma2(D2[3], pB, vb.y);
            fma2(D2[4], pA, vc.x); fma2(D2[5], pB, vc.y);
        }
        __syncthreads();
        if (ti + 2 < NT) {
            const int kb2 = (ti + 2) * KTE;
            float* edst = sm.em[buf];
            float* pdst = sm.proj[buf];
#pragma unroll
            for (int r = 0; r < 8; r++) {
                const int j = t + r * 128;
                const int qq = j >> 8, rem = j & 255;
                const int k = rem >> 4, cl = (rem & 15) * 4;
                cp16(&edst[qq * 1024 + k * 64 + cl],
                     &em[em_base + (size_t)qq * (Nn * CEQ) + (kb2 + k) * CEQ + cl]);
            }
#pragma unroll
            for (int r = 0; r < 6; r++) {
                const int j = t + r * 128;
                const int k = j / 48, rem = j % 48;
                const int d = rem >> 4, cl = (rem & 15) * 4;
                cp16(&pdst[k * 192 + d * 64 + cl],
                     &g_proj_e[((size_t)(b * Nn + kb2 + k) * 3 + d) * CEQ + cl]);
            }
            cp_commit();
        }
    }

    // reduce across the 2 ksub lanes
    {
#pragma unroll
        for (int j = 0; j < 2; j++) {
            u64 v;
            v = __shfl_xor_sync(0xffffffffu, S2[j], 16); add2(S2[j], v);
            v = __shfl_xor_sync(0xffffffffu, Q2[j], 16); add2(Q2[j], v);
        }
#pragma unroll
        for (int r = 0; r < 6; r++) {
            u64 v;
            v = __shfl_xor_sync(0xffffffffu, D2[r], 16); add2(D2[r], v);
        }
    }

    // scaled rows -> smem overlay: rows [12][68] at em[0][0..816)
    float* rows = sm.em[0];
    if (ksub == 0) {
        const float2 sA = unpack2(S2[0]), sB = unpack2(S2[1]);
        const float2 qA = unpack2(Q2[0]), qB = unpack2(Q2[1]);
        const float Sv[4] = {sA.x, sA.y, sB.x, sB.y};
        const float Qv[4] = {qA.x, qA.y, qB.x, qB.y};
        float sc[4];
#pragma unroll
        for (int j = 0; j < 4; j++) {
            const float iv = 1.0f / Sv[j];
            sc[j] = sqrtf(Qv[j]) * iv * iv;
        }
#pragma unroll
        for (int d = 0; d < 3; d++) {
            const float2 dA = unpack2(D2[d * 2]), dB = unpack2(D2[d * 2 + 1]);
            float4 o;
            o.x = dA.x * sc[0]; o.y = dA.y * sc[1];
            o.z = dB.x * sc[2]; o.w = dB.y * sc[3];
            *(float4*)&rows[(wid * 3 + d) * 68 + c4 * 4] = o;
        }
    }

    // load W_eo transposed into smem overlay: Wt[c][o], stride 68, at em[0]+1024
    float* Wt = sm.em[0] + 1024;
#pragma unroll
    for (int r = 0; r < 8; r++) {
        const int j = t + r * 128;        // 1024 float4
        const int o = j >> 4, cq = (j & 15) * 4;
        const float4 w = *(const float4*)&W_eo[o * 64 + cq];
        Wt[(cq + 0) * 68 + o] = w.x;
        Wt[(cq + 1) * 68 + o] = w.y;
        Wt[(cq + 2) * 68 + o] = w.z;
        Wt[(cq + 3) * 68 + o] = w.w;
    }
    __syncthreads();

    // in-CTA output projection: warp handles rows [wid*3, wid*3+3);
    // lane covers outputs o = lane*2, lane*2+1
    const u64 bias2 = *(const u64*)&b_eo[lane * 2];
#pragma unroll
    for (int d = 0; d < 3; d++) {
        const int r = wid * 3 + d;
        u64 acc = 0ull;
#pragma unroll
        for (int cq = 0; cq < 16; cq++) {
            const float4 rv = *(const float4*)&rows[r * 68 + cq * 4];
            fma2(acc, pack2(rv.x, rv.x), *(const u64*)&Wt[(cq * 4 + 0) * 68 + lane * 2]);
            fma2(acc, pack2(rv.y, rv.y), *(const u64*)&Wt[(cq * 4 + 1) * 68 + lane * 2]);
            fma2(acc, pack2(rv.z, rv.z), *(const u64*)&Wt[(cq * 4 + 2) * 68 + lane * 2]);
            fma2(acc, pack2(rv.w, rv.w), *(const u64*)&Wt[(cq * 4 + 3) * 68 + lane * 2]);
        }
        add2(acc, bias2);
        const float2 ov = unpack2(acc);
        float* op = out_equi + (((size_t)(b * Nn + q) * 3 + d) * CEQ);
        *(float2*)&op[lane * 2] = ov;
    }
}

// ---------------------------------------------------------------------------
// Inv attention, 512 CTAs x 128 threads (R13 2-stage version).
// ---------------------------------------------------------------------------
struct __align__(16) InvSm {
    float hf[2][8 * 260];
    float mask[8 * 256];
};

__global__ void __launch_bounds__(128, 4) inv_attn_kernel(
    const float* __restrict__ im,      // [B,N,N,16]
    const int*   __restrict__ adj)     // [B,N,N]
{
    __shared__ InvSm sm;
    const int id = blockIdx.x;
    const int t = threadIdx.x;
    const int wid = t >> 5, lane = t & 31;
    const int hg = id & 1, qg = (id >> 1) & 31, b = id >> 6;
    const int h = lane & 7;
    const int ksub = lane >> 3;
    const int hbase = hg * 8;
    const int q0 = qg * 8 + wid * 2;

#pragma unroll
    for (int j = 0; j < 2; j++) {
        const int* arow = adj + (size_t)(b * Nn + q0 + j) * Nn;
        const int4 a0 = *(const int4*)&arow[lane * 8];
        const int4 a1 = *(const int4*)&arow[lane * 8 + 4];
        const bool c0 = a0.x != 0, c1 = a0.y != 0, c2 = a0.z != 0, c3 = a0.w != 0;
        const bool c5 = a1.x != 0, c6 = a1.y != 0, c7 = a1.z != 0, c8 = a1.w != 0;
        const unsigned any = __ballot_sync(0xffffffffu,
            c0 | c1 | c2 | c3 | c5 | c6 | c7 | c8);
        const float neg = any ? -1e30f : 0.0f;
        float4 m0, m1;
        m0.x = c0 ? 0.0f : neg; m0.y = c1 ? 0.0f : neg;
        m0.z = c2 ? 0.0f : neg; m0.w = c3 ? 0.0f : neg;
        m1.x = c5 ? 0.0f : neg; m1.y = c6 ? 0.0f : neg;
        m1.z = c7 ? 0.0f : neg; m1.w = c8 ? 0.0f : neg;
        *(float4*)&sm.mask[(wid * 2 + j) * 256 + lane * 8] = m0;
        *(float4*)&sm.mask[(wid * 2 + j) * 256 + lane * 8 + 4] = m1;
    }
    // prefetch tile 0
#pragma unroll
    for (int r = 0; r < 4; r++) {
        const int j = t + r * 128;
        const int k = j >> 5, rem = j & 31;
        const int hh = rem >> 2, e4 = (rem & 3) * 4;
        cp16(&sm.hf[0][hh * 260 + k * 16 + e4],
             &g_proj_i[(size_t)(b * Nn + k) * DIN + (hbase + hh) * 16 + e4]);
    }
    cp_commit();

    float S0 = 0.0f, SQ0 = 0.0f, S1 = 0.0f, SQ1 = 0.0f;
    u64 Aa[8], Ab[8];
#pragma unroll
    for (int e = 0; e < 8; e++) { Aa[e] = 0ull; Ab[e] = 0ull; }

    const float* imq0 = im + (size_t)(b * Nn + q0) * (Nn * 16) + hbase + h;
    const float* imq1 = imq0 + Nn * 16;
    const float* mq0 = sm.mask + (wid * 2) * 256;
    const float* mq1 = mq0 + 256;

    int buf = 0;
#pragma unroll 1
    for (int ti = 0; ti < Nn / KTI; ti++) {
        if (ti + 1 < Nn / KTI) {
            const int kb2 = (ti + 1) * KTI;
#pragma unroll
            for (int r = 0; r < 4; r++) {
                const int j = t + r * 128;
                const int k = j >> 5, rem = j & 31;
                const int hh = rem >> 2, e4 = (rem & 3) * 4;
                cp16(&sm.hf[buf ^ 1][hh * 260 + k * 16 + e4],
                     &g_proj_i[(size_t)(b * Nn + kb2 + k) * DIN + (hbase + hh) * 16 + e4]);
            }
            cp_commit();
            cp_wait<1>();
        } else {
            cp_wait<0>();
        }
        __syncthreads();
        const float* hs = sm.hf[buf];
        const int kb = ti * KTI;
#pragma unroll
        for (int it = 0; it < KTI / 4; it++) {
            const int kl = it * 4 + ksub;
            const int k = kb + kl;
            const float x0 = imq0[(size_t)k * 16];
            const float x1 = imq1[(size_t)k * 16];
            const float p0 = ex2f(fmaf(x0, L2E, mq0[k]));
            const float p1 = ex2f(fmaf(x1, L2E, mq1[k]));
            S0 += p0; SQ0 = fmaf(p0, p0, SQ0);
            S1 += p1; SQ1 = fmaf(p1, p1, SQ1);
            const u64 pp0 = pack2(p0, p0);
            const u64 pp1 = pack2(p1, p1);
            const float* hk = hs + h * 260 + kl * 16;
            const ulonglong2 v0 = *(const ulonglong2*)&hk[0];
            const ulonglong2 v1 = *(const ulonglong2*)&hk[4];
            const ulonglong2 v2 = *(const ulonglong2*)&hk[8];
            const ulonglong2 v3 = *(const ulonglong2*)&hk[12];
            fma2(Aa[0], pp0, v0.x); fma2(Aa[1], pp0, v0.y);
            fma2(Aa[2], pp0, v1.x); fma2(Aa[3], pp0, v1.y);
            fma2(Aa[4], pp0, v2.x); fma2(Aa[5], pp0, v2.y);
            fma2(Aa[6], pp0, v3.x); fma2(Aa[7], pp0, v3.y);
            fma2(Ab[0], pp1, v0.x); fma2(Ab[1], pp1, v0.y);
            fma2(Ab[2], pp1, v1.x); fma2(Ab[3], pp1, v1.y);
            fma2(Ab[4], pp1, v2.x); fma2(Ab[5], pp1, v2.y);
            fma2(Ab[6], pp1, v3.x); fma2(Ab[7], pp1, v3.y);
        }
        __syncthreads();
        buf ^= 1;
    }

#pragma unroll
    for (int m = 8; m <= 16; m <<= 1) {
        S0  += __shfl_xor_sync(0xffffffffu, S0,  m);
        SQ0 += __shfl_xor_sync(0xffffffffu, SQ0, m);
        S1  += __shfl_xor_sync(0xffffffffu, S1,  m);
        SQ1 += __shfl_xor_sync(0xffffffffu, SQ1, m);
#pragma unroll
        for (int e = 0; e < 8; e++) {
            u64 v;
            v = __shfl_xor_sync(0xffffffffu, Aa[e], m); add2(Aa[e], v);
            v = __shfl_xor_sync(0xffffffffu, Ab[e], m); add2(Ab[e], v);
        }
    }

    if (ksub == 0) {
        const float i0 = 1.0f / S0, i1 = 1.0f / S1;
        const float sc0 = sqrtf(SQ0) * i0 * i0;
        const float sc1 = sqrtf(SQ1) * i1 * i1;
        float* o0 = g_out_i + (size_t)(b * Nn + q0) * DIN + (hbase + h) * 16;
        float* o1 = o0 + DIN;
#pragma unroll
        for (int e4 = 0; e4 < 4; e4++) {
            const float2 lo0 = unpack2(Aa[e4 * 2]);
            const float2 hi0 = unpack2(Aa[e4 * 2 + 1]);
            const float2 lo1 = unpack2(Ab[e4 * 2]);
            const float2 hi1 = unpack2(Ab[e4 * 2 + 1]);
            float4 v0, v1;
            v0.x = lo0.x * sc0; v0.y = lo0.y * sc0;
            v0.z = hi0.x * sc0; v0.w = hi0.y * sc0;
            v1.x = lo1.x * sc1; v1.y = lo1.y * sc1;
            v1.z = hi1.x * sc1; v1.w = hi1.y * sc1;
            *(float4*)&o0[e4 * 4] = v0;
            *(float4*)&o1[e4 * 4] = v1;
        }
    }
}

// ---------------------------------------------------------------------------
// Output kernel (inv only): 128 CTAs, 32 m-tiles x 4 n-tiles
// ---------------------------------------------------------------------------
__global__ void __launch_bounds__(256) out_kernel(
    const float* __restrict__ W_out, const float* __restrict__ b_out,
    float* __restrict__ out)
{
    __shared__ __align__(16) float sm[2 * 2 * 16 * 68];
    const int id = blockIdx.x;
    gemm_tile64(g_out_i, W_out, b_out, out + (size_t)Bsz * Nn * 3 * CEQ,
                DIN, DIN, (id >> 2) * 64, (id & 3) * 64, sm);
}

// ---------------------------------------------------------------------------
// Launch: two-stream fork/join (graph-capturable pattern).
// ---------------------------------------------------------------------------
extern "C" void kernel_launch(void* const* d_in, const int* in_sizes, int n_in,
                              void* d_out, int out_size) {
    const float* v_equi     = (const float*)d_in[0];
    const float* v_inv      = (const float*)d_in[1];
    const float* em         = (const float*)d_in[2];
    const float* im         = (const float*)d_in[3];
    const int*   adj        = (const int*)  d_in[4];
    const float* W_coord    = (const float*)d_in[5];
    const float* W_equi_out = (const float*)d_in[6];
    const float* b_equi_out = (const float*)d_in[7];
    const float* W_in       = (const float*)d_in[8];
    const float* b_in       = (const float*)d_in[9];
    const float* W_out      = (const float*)d_in[10];
    const float* b_out      = (const float*)d_in[11];
    float* out = (float*)d_out;

    static cudaStream_t s2 = nullptr;
    static cudaEvent_t ev_fork = nullptr, ev_join = nullptr;
    if (s2 == nullptr) {
        cudaStreamCreateWithFlags(&s2, cudaStreamNonBlocking);
        cudaEventCreateWithFlags(&ev_fork, cudaEventDisableTiming);
        cudaEventCreateWithFlags(&ev_join, cudaEventDisableTiming);
    }

    // fork: s2 branches off the (capture) null stream
    cudaEventRecord(ev_fork, 0);
    cudaStreamWaitEvent(s2, ev_fork, 0);

    // stream B: inv chain
    prep_i_kernel<<<128, 256, 0, s2>>>(v_inv, W_in, b_in);
    inv_attn_kernel<<<512, 128, 0, s2>>>(im, adj);
    out_kernel<<<128, 256, 0, s2>>>(W_out, b_out, out);
    cudaEventRecord(ev_join, s2);

    // stream A (null): equi chain
    prep_e_kernel<<<96, 256>>>(v_equi, W_coord);
    equi_attn_kernel<<<512, 128>>>(em, adj, W_equi_out, b_equi_out, out);

    // join
    cudaStreamWaitEvent(0, ev_join, 0);
}

// round 16
// speedup vs baseline: 1.3509x; 1.0379x over previous
#include <cuda_runtime.h>
#include <cuda_bf16.h>
#include <cstdint>

// ---------------------------------------------------------------------------
// SemlaLayer: equi + inv attention, B=8, N=256, D_EQUI=64, H=16, D_HEAD=16
// Two-stream overlap: [null] prep_e -> equi_attn(em via cp.async, fused out)
//                     [s2]   prep_i -> inv_attn -> out_inv
// GEMMs use distance-2 register prefetch (LDG for step s+2 issued at step s).
// ---------------------------------------------------------------------------
#define Bsz 8
#define Nn  256
#define CEQ 64
#define DIN 256
#define L2E 1.4426950408889634f
#define KTE 16
#define KTI 16

typedef unsigned long long u64;

// Scratch (device globals; no allocation allowed)
__device__ __align__(128) float g_proj_e[Bsz * Nn * 3 * CEQ];
__device__ __align__(128) float g_proj_i[Bsz * Nn * DIN];
__device__ __align__(128) float g_out_i [Bsz * Nn * DIN];

__device__ __forceinline__ float ex2f(float x) {
    float r;
    asm("ex2.approx.ftz.f32 %0, %1;" : "=f"(r) : "f"(x));
    return r;
}
__device__ __forceinline__ u64 pack2(float lo, float hi) {
    u64 r;
    asm("mov.b64 %0, {%1, %2};" : "=l"(r) : "f"(lo), "f"(hi));
    return r;
}
__device__ __forceinline__ float2 unpack2(u64 v) {
    float2 f;
    asm("mov.b64 {%0, %1}, %2;" : "=f"(f.x), "=f"(f.y) : "l"(v));
    return f;
}
__device__ __forceinline__ void fma2(u64& d, u64 a, u64 b) {
    asm("fma.rn.f32x2 %0, %1, %2, %3;" : "=l"(d) : "l"(a), "l"(b), "l"(d));
}
__device__ __forceinline__ void add2(u64& d, u64 a) {
    asm("add.rn.f32x2 %0, %1, %2;" : "=l"(d) : "l"(a), "l"(d));
}

__device__ __forceinline__ void cp16(float* dst_smem, const float* src) {
    uint32_t d = (uint32_t)__cvta_generic_to_shared(dst_smem);
    asm volatile("cp.async.cg.shared.global [%0], [%1], 16;" :: "r"(d), "l"(src) : "memory");
}
__device__ __forceinline__ void cp_commit() {
    asm volatile("cp.async.commit_group;" ::: "memory");
}
template <int N> __device__ __forceinline__ void cp_wait() {
    asm volatile("cp.async.wait_group %0;" :: "n"(N) : "memory");
}

// ---------------------------------------------------------------------------
// f32x2 GEMM tile: C[m_base:+64, n_base:+64] = X @ W^T (+bias)
// 256 threads, BK=16, double-buffered smem, packed row-pair accumulators.
// Distance-2 LDG prefetch: load for step s+2 issued at step s (px/pw rotate).
// ---------------------------------------------------------------------------
__device__ __forceinline__ void gemm_tile64(
    const float* __restrict__ X, const float* __restrict__ W,
    const float* __restrict__ bias, float* __restrict__ C,
    int Nout, int K, int m_base, int n_base, float* sm)
{
    const int t = threadIdx.x;
    const int tx = t & 15, ty = t >> 4;
    const int lm = t >> 2;
    const int lk = (t & 3) * 4;

    u64 acc[2][4];
#pragma unroll
    for (int i = 0; i < 2; i++)
#pragma unroll
        for (int j = 0; j < 4; j++) acc[i][j] = 0ull;

    const float* Xrow = &X[(size_t)(m_base + lm) * K + lk];
    const float* Wrow = &W[(size_t)(n_base + lm) * K + lk];
    const int nsteps = K / 16;

    // tile 0 -> buf0 directly
    {
        float4 vx = *(const float4*)Xrow;
        float4 vw = *(const float4*)Wrow;
        float* Xs = sm;
        float* Ws = sm + 1088;
        Xs[(lk + 0) * 68 + lm] = vx.x; Xs[(lk + 1) * 68 + lm] = vx.y;
        Xs[(lk + 2) * 68 + lm] = vx.z; Xs[(lk + 3) * 68 + lm] = vx.w;
        Ws[(lk + 0) * 68 + lm] = vw.x; Ws[(lk + 1) * 68 + lm] = vw.y;
        Ws[(lk + 2) * 68 + lm] = vw.z; Ws[(lk + 3) * 68 + lm] = vw.w;
    }
    // prefetch regs: px[(s+1)&1] consumed (stored to smem) at step s.
    float4 px[2], pw[2];
    if (nsteps > 1) {
        px[1] = *(const float4*)(Xrow + 16);
        pw[1] = *(const float4*)(Wrow + 16);
    }
    __syncthreads();

#pragma unroll 2
    for (int s = 0; s < nsteps; s++) {
        if (s + 2 < nsteps) {
            px[s & 1] = *(const float4*)(Xrow + (s + 2) * 16);
            pw[s & 1] = *(const float4*)(Wrow + (s + 2) * 16);
        }
        const float* Xs = sm + (s & 1) * 2176;
        const float* Ws = Xs + 1088;
#pragma unroll
        for (int kk = 0; kk < 16; kk++) {
            const ulonglong2 ax = *(const ulonglong2*)&Xs[kk * 68 + ty * 4];
            const float4 bv = *(const float4*)&Ws[kk * 68 + tx * 4];
            const u64 b0 = pack2(bv.x, bv.x), b1 = pack2(bv.y, bv.y);
            const u64 b2 = pack2(bv.z, bv.z), b3 = pack2(bv.w, bv.w);
            fma2(acc[0][0], ax.x, b0); fma2(acc[0][1], ax.x, b1);
            fma2(acc[0][2], ax.x, b2); fma2(acc[0][3], ax.x, b3);
            fma2(acc[1][0], ax.y, b0); fma2(acc[1][1], ax.y, b1);
            fma2(acc[1][2], ax.y, b2); fma2(acc[1][3], ax.y, b3);
        }
        if (s + 1 < nsteps) {
            const float4 nx = px[(s + 1) & 1];
            const float4 nw = pw[(s + 1) & 1];
            float* Xd = sm + ((s + 1) & 1) * 2176;
            float* Wd = Xd + 1088;
            Xd[(lk + 0) * 68 + lm] = nx.x; Xd[(lk + 1) * 68 + lm] = nx.y;
            Xd[(lk + 2) * 68 + lm] = nx.z; Xd[(lk + 3) * 68 + lm] = nx.w;
            Wd[(lk + 0) * 68 + lm] = nw.x; Wd[(lk + 1) * 68 + lm] = nw.y;
            Wd[(lk + 2) * 68 + lm] = nw.z; Wd[(lk + 3) * 68 + lm] = nw.w;
        }
        __syncthreads();
    }

    float4 bvec;
    if (bias) bvec = *(const float4*)&bias[n_base + tx * 4];
    else      bvec = make_float4(0.f, 0.f, 0.f, 0.f);
#pragma unroll
    for (int p = 0; p < 2; p++) {
        float4 lo, hi;
        float2 f;
        f = unpack2(acc[p][0]); lo.x = f.x + bvec.x; hi.x = f.y + bvec.x;
        f = unpack2(acc[p][1]); lo.y = f.x + bvec.y; hi.y = f.y + bvec.y;
        f = unpack2(acc[p][2]); lo.z = f.x + bvec.z; hi.z = f.y + bvec.z;
        f = unpack2(acc[p][3]); lo.w = f.x + bvec.w; hi.w = f.y + bvec.w;
        const int m = m_base + ty * 4 + p * 2;
        *(float4*)&C[(size_t)m * Nout + n_base + tx * 4] = lo;
        *(float4*)&C[(size_t)(m + 1) * Nout + n_base + tx * 4] = hi;
    }
}

// ---------------------------------------------------------------------------
// prep_e: equi input GEMM (96 CTAs).   prep_i: inv input GEMM (128 CTAs).
// ---------------------------------------------------------------------------
__global__ void __launch_bounds__(256) prep_e_kernel(
    const float* __restrict__ v_equi, const float* __restrict__ W_coord)
{
    __shared__ __align__(16) float sm[2 * 2 * 16 * 68];
    gemm_tile64(v_equi, W_coord, nullptr, g_proj_e, CEQ, CEQ, blockIdx.x * 64, 0, sm);
}

__global__ void __launch_bounds__(256) prep_i_kernel(
    const float* __restrict__ v_inv,
    const float* __restrict__ W_in, const float* __restrict__ b_in)
{
    __shared__ __align__(16) float sm[2 * 2 * 16 * 68];
    const int id = blockIdx.x;                  // 32 m-tiles x 4 n-tiles
    gemm_tile64(v_inv, W_in, b_in, g_proj_i, DIN, DIN, (id >> 2) * 64, (id & 3) * 64, sm);
}

// ---------------------------------------------------------------------------
// Equi attention, 512 CTAs x 128 threads. Warp owns ONE q (4 q / CTA).
// em streamed through smem via cp.async (2-stage). Fused output projection.
// ---------------------------------------------------------------------------
struct __align__(16) EquiSm {
    float em[2][4096];     // [q][k][ch] : q*1024 + k*64 + c ; overlay rows/Wt after
    float proj[2][3072];   // [k][d*64 + c]
    float mask[4 * 256];
};

__global__ void __launch_bounds__(128, 3) equi_attn_kernel(
    const float* __restrict__ em,      // [B,N,N,64]
    const int*   __restrict__ adj,     // [B,N,N]
    const float* __restrict__ W_eo,    // [64,64]
    const float* __restrict__ b_eo,    // [64]
    float* __restrict__ out_equi)      // d_out equi part [B,N,3,64]
{
    __shared__ EquiSm sm;
    const int bx = blockIdx.x;
    const int t = threadIdx.x;
    const int wid = t >> 5, lane = t & 31;
    const int c4 = lane & 15;
    const int ksub = lane >> 4;
    const int qg = bx & 63, b = bx >> 6;
    const int q = qg * 4 + wid;

    // mask from adj: warp computes its q-row
    {
        const int* arow = adj + (size_t)(b * Nn + q) * Nn;
        const int4 a0 = *(const int4*)&arow[lane * 8];
        const int4 a1 = *(const int4*)&arow[lane * 8 + 4];
        const bool c0 = a0.x != 0, c1 = a0.y != 0, c2 = a0.z != 0, c3 = a0.w != 0;
        const bool c5 = a1.x != 0, c6 = a1.y != 0, c7 = a1.z != 0, c8 = a1.w != 0;
        const unsigned any = __ballot_sync(0xffffffffu,
            c0 | c1 | c2 | c3 | c5 | c6 | c7 | c8);
        const float neg = any ? -1e30f : 0.0f;
        float4 m0, m1;
        m0.x = c0 ? 0.0f : neg; m0.y = c1 ? 0.0f : neg;
        m0.z = c2 ? 0.0f : neg; m0.w = c3 ? 0.0f : neg;
        m1.x = c5 ? 0.0f : neg; m1.y = c6 ? 0.0f : neg;
        m1.z = c7 ? 0.0f : neg; m1.w = c8 ? 0.0f : neg;
        *(float4*)&sm.mask[wid * 256 + lane * 8] = m0;
        *(float4*)&sm.mask[wid * 256 + lane * 8 + 4] = m1;
    }

    const size_t em_base = (size_t)(b * Nn + qg * 4) * (Nn * CEQ);

    // prefetch stages 0,1: em tile (1024 f4, 8/thread) + proj tile (768 f4, 6/thread)
#pragma unroll
    for (int pre = 0; pre < 2; pre++) {
#pragma unroll
        for (int r = 0; r < 8; r++) {
            const int j = t + r * 128;
            const int qq = j >> 8, rem = j & 255;
            const int k = rem >> 4, cl = (rem & 15) * 4;
            cp16(&sm.em[pre][qq * 1024 + k * 64 + cl],
                 &em[em_base + (size_t)qq * (Nn * CEQ) + (pre * KTE + k) * CEQ + cl]);
        }
#pragma unroll
        for (int r = 0; r < 6; r++) {
            const int j = t + r * 128;
            const int k = j / 48, rem = j % 48;
            const int d = rem >> 4, cl = (rem & 15) * 4;
            cp16(&sm.proj[pre][k * 192 + d * 64 + cl],
                 &g_proj_e[((size_t)(b * Nn + pre * KTE + k) * 3 + d) * CEQ + cl]);
        }
        cp_commit();
    }

    u64 S2[2], Q2[2], D2[6];
#pragma unroll
    for (int j = 0; j < 2; j++) { S2[j] = 0ull; Q2[j] = 0ull; }
#pragma unroll
    for (int r = 0; r < 6; r++) D2[r] = 0ull;

    const float* mq = sm.mask + wid * 256;

    const int NT = Nn / KTE;   // 16
#pragma unroll 1
    for (int ti = 0; ti < NT; ti++) {
        if (ti + 1 < NT) cp_wait<1>(); else cp_wait<0>();
        __syncthreads();
        const int buf = ti & 1;
        const float* emL = sm.em[buf] + wid * 1024;
        const float* ps = sm.proj[buf];
        const int kb = ti * KTE;
#pragma unroll
        for (int it = 0; it < KTE / 2; it++) {
            const int kl = it * 2 + ksub;
            const int k = kb + kl;
            const float4 x = *(const float4*)&emL[kl * 64 + c4 * 4];
            const float mk = mq[k];
            const float a0 = ex2f(fmaf(x.x, L2E, mk));
            const float a1 = ex2f(fmaf(x.y, L2E, mk));
            const float a2 = ex2f(fmaf(x.z, L2E, mk));
            const float a3 = ex2f(fmaf(x.w, L2E, mk));
            const u64 pA = pack2(a0, a1), pB = pack2(a2, a3);
            add2(S2[0], pA);      add2(S2[1], pB);
            fma2(Q2[0], pA, pA);  fma2(Q2[1], pB, pB);
            const ulonglong2 va = *(const ulonglong2*)&ps[kl * 192 +   0 + c4 * 4];
            const ulonglong2 vb = *(const ulonglong2*)&ps[kl * 192 +  64 + c4 * 4];
            const ulonglong2 vc = *(const ulonglong2*)&ps[kl * 192 + 128 + c4 * 4];
            fma2(D2[0], pA, va.x); fma2(D2[1], pB, va.y);
            fma2(D2[2], pA, vb.x); fma2(D2[3], pB, vb.y);
            fma2(D2[4], pA, vc.x); fma2(D2[5], pB, vc.y);
        }
        __syncthreads();
        if (ti + 2 < NT) {
            const int kb2 = (ti + 2) * KTE;
            float* edst = sm.em[buf];
            float* pdst = sm.proj[buf];
#pragma unroll
            for (int r = 0; r < 8; r++) {
                const int j = t + r * 128;
                const int qq = j >> 8, rem = j & 255;
                const int k = rem >> 4, cl = (rem & 15) * 4;
                cp16(&edst[qq * 1024 + k * 64 + cl],
                     &em[em_base + (size_t)qq * (Nn * CEQ) + (kb2 + k) * CEQ + cl]);
            }
#pragma unroll
            for (int r = 0; r < 6; r++) {
                const int j = t + r * 128;
                const int k = j / 48, rem = j % 48;
                const int d = rem >> 4, cl = (rem & 15) * 4;
                cp16(&pdst[k * 192 + d * 64 + cl],
                     &g_proj_e[((size_t)(b * Nn + kb2 + k) * 3 + d) * CEQ + cl]);
            }
            cp_commit();
        }
    }

    // reduce across the 2 ksub lanes
    {
#pragma unroll
        for (int j = 0; j < 2; j++) {
            u64 v;
            v = __shfl_xor_sync(0xffffffffu, S2[j], 16); add2(S2[j], v);
            v = __shfl_xor_sync(0xffffffffu, Q2[j], 16); add2(Q2[j], v);
        }
#pragma unroll
        for (int r = 0; r < 6; r++) {
            u64 v;
            v = __shfl_xor_sync(0xffffffffu, D2[r], 16); add2(D2[r], v);
        }
    }

    // scaled rows -> smem overlay: rows [12][68] at em[0][0..816)
    float* rows = sm.em[0];
    if (ksub == 0) {
        const float2 sA = unpack2(S2[0]), sB = unpack2(S2[1]);
        const float2 qA = unpack2(Q2[0]), qB = unpack2(Q2[1]);
        const float Sv[4] = {sA.x, sA.y, sB.x, sB.y};
        const float Qv[4] = {qA.x, qA.y, qB.x, qB.y};
        float sc[4];
#pragma unroll
        for (int j = 0; j < 4; j++) {
            const float iv = 1.0f / Sv[j];
            sc[j] = sqrtf(Qv[j]) * iv * iv;
        }
#pragma unroll
        for (int d = 0; d < 3; d++) {
            const float2 dA = unpack2(D2[d * 2]), dB = unpack2(D2[d * 2 + 1]);
            float4 o;
            o.x = dA.x * sc[0]; o.y = dA.y * sc[1];
            o.z = dB.x * sc[2]; o.w = dB.y * sc[3];
            *(float4*)&rows[(wid * 3 + d) * 68 + c4 * 4] = o;
        }
    }

    // load W_eo transposed into smem overlay: Wt[c][o], stride 68, at em[0]+1024
    float* Wt = sm.em[0] + 1024;
#pragma unroll
    for (int r = 0; r < 8; r++) {
        const int j = t + r * 128;        // 1024 float4
        const int o = j >> 4, cq = (j & 15) * 4;
        const float4 w = *(const float4*)&W_eo[o * 64 + cq];
        Wt[(cq + 0) * 68 + o] = w.x;
        Wt[(cq + 1) * 68 + o] = w.y;
        Wt[(cq + 2) * 68 + o] = w.z;
        Wt[(cq + 3) * 68 + o] = w.w;
    }
    __syncthreads();

    // in-CTA output projection: warp handles rows [wid*3, wid*3+3);
    // lane covers outputs o = lane*2, lane*2+1
    const u64 bias2 = *(const u64*)&b_eo[lane * 2];
#pragma unroll
    for (int d = 0; d < 3; d++) {
        const int r = wid * 3 + d;
        u64 acc = 0ull;
#pragma unroll
        for (int cq = 0; cq < 16; cq++) {
            const float4 rv = *(const float4*)&rows[r * 68 + cq * 4];
            fma2(acc, pack2(rv.x, rv.x), *(const u64*)&Wt[(cq * 4 + 0) * 68 + lane * 2]);
            fma2(acc, pack2(rv.y, rv.y), *(const u64*)&Wt[(cq * 4 + 1) * 68 + lane * 2]);
            fma2(acc, pack2(rv.z, rv.z), *(const u64*)&Wt[(cq * 4 + 2) * 68 + lane * 2]);
            fma2(acc, pack2(rv.w, rv.w), *(const u64*)&Wt[(cq * 4 + 3) * 68 + lane * 2]);
        }
        add2(acc, bias2);
        const float2 ov = unpack2(acc);
        float* op = out_equi + (((size_t)(b * Nn + q) * 3 + d) * CEQ);
        *(float2*)&op[lane * 2] = ov;
    }
}

// ---------------------------------------------------------------------------
// Inv attention, 512 CTAs x 128 threads (2-stage cp.async).
// ---------------------------------------------------------------------------
struct __align__(16) InvSm {
    float hf[2][8 * 260];
    float mask[8 * 256];
};

__global__ void __launch_bounds__(128, 4) inv_attn_kernel(
    const float* __restrict__ im,      // [B,N,N,16]
    const int*   __restrict__ adj)     // [B,N,N]
{
    __shared__ InvSm sm;
    const int id = blockIdx.x;
    const int t = threadIdx.x;
    const int wid = t >> 5, lane = t & 31;
    const int hg = id & 1, qg = (id >> 1) & 31, b = id >> 6;
    const int h = lane & 7;
    const int ksub = lane >> 3;
    const int hbase = hg * 8;
    const int q0 = qg * 8 + wid * 2;

#pragma unroll
    for (int j = 0; j < 2; j++) {
        const int* arow = adj + (size_t)(b * Nn + q0 + j) * Nn;
        const int4 a0 = *(const int4*)&arow[lane * 8];
        const int4 a1 = *(const int4*)&arow[lane * 8 + 4];
        const bool c0 = a0.x != 0, c1 = a0.y != 0, c2 = a0.z != 0, c3 = a0.w != 0;
        const bool c5 = a1.x != 0, c6 = a1.y != 0, c7 = a1.z != 0, c8 = a1.w != 0;
        const unsigned any = __ballot_sync(0xffffffffu,
            c0 | c1 | c2 | c3 | c5 | c6 | c7 | c8);
        const float neg = any ? -1e30f : 0.0f;
        float4 m0, m1;
        m0.x = c0 ? 0.0f : neg; m0.y = c1 ? 0.0f : neg;
        m0.z = c2 ? 0.0f : neg; m0.w = c3 ? 0.0f : neg;
        m1.x = c5 ? 0.0f : neg; m1.y = c6 ? 0.0f : neg;
        m1.z = c7 ? 0.0f : neg; m1.w = c8 ? 0.0f : neg;
        *(float4*)&sm.mask[(wid * 2 + j) * 256 + lane * 8] = m0;
        *(float4*)&sm.mask[(wid * 2 + j) * 256 + lane * 8 + 4] = m1;
    }
    // prefetch tile 0
#pragma unroll
    for (int r = 0; r < 4; r++) {
        const int j = t + r * 128;
        const int k = j >> 5, rem = j & 31;
        const int hh = rem >> 2, e4 = (rem & 3) * 4;
        cp16(&sm.hf[0][hh * 260 + k * 16 + e4],
             &g_proj_i[(size_t)(b * Nn + k) * DIN + (hbase + hh) * 16 + e4]);
    }
    cp_commit();

    float S0 = 0.0f, SQ0 = 0.0f, S1 = 0.0f, SQ1 = 0.0f;
    u64 Aa[8], Ab[8];
#pragma unroll
    for (int e = 0; e < 8; e++) { Aa[e] = 0ull; Ab[e] = 0ull; }

    const float* imq0 = im + (size_t)(b * Nn + q0) * (Nn * 16) + hbase + h;
    const float* imq1 = imq0 + Nn * 16;
    const float* mq0 = sm.mask + (wid * 2) * 256;
    const float* mq1 = mq0 + 256;

    int buf = 0;
#pragma unroll 1
    for (int ti = 0; ti < Nn / KTI; ti++) {
        if (ti + 1 < Nn / KTI) {
            const int kb2 = (ti + 1) * KTI;
#pragma unroll
            for (int r = 0; r < 4; r++) {
                const int j = t + r * 128;
                const int k = j >> 5, rem = j & 31;
                const int hh = rem >> 2, e4 = (rem & 3) * 4;
                cp16(&sm.hf[buf ^ 1][hh * 260 + k * 16 + e4],
                     &g_proj_i[(size_t)(b * Nn + kb2 + k) * DIN + (hbase + hh) * 16 + e4]);
            }
            cp_commit();
            cp_wait<1>();
        } else {
            cp_wait<0>();
        }
        __syncthreads();
        const float* hs = sm.hf[buf];
        const int kb = ti * KTI;
#pragma unroll
        for (int it = 0; it < KTI / 4; it++) {
            const int kl = it * 4 + ksub;
            const int k = kb + kl;
            const float x0 = imq0[(size_t)k * 16];
            const float x1 = imq1[(size_t)k * 16];
            const float p0 = ex2f(fmaf(x0, L2E, mq0[k]));
            const float p1 = ex2f(fmaf(x1, L2E, mq1[k]));
            S0 += p0; SQ0 = fmaf(p0, p0, SQ0);
            S1 += p1; SQ1 = fmaf(p1, p1, SQ1);
            const u64 pp0 = pack2(p0, p0);
            const u64 pp1 = pack2(p1, p1);
            const float* hk = hs + h * 260 + kl * 16;
            const ulonglong2 v0 = *(const ulonglong2*)&hk[0];
            const ulonglong2 v1 = *(const ulonglong2*)&hk[4];
            const ulonglong2 v2 = *(const ulonglong2*)&hk[8];
            const ulonglong2 v3 = *(const ulonglong2*)&hk[12];
            fma2(Aa[0], pp0, v0.x); fma2(Aa[1], pp0, v0.y);
            fma2(Aa[2], pp0, v1.x); fma2(Aa[3], pp0, v1.y);
            fma2(Aa[4], pp0, v2.x); fma2(Aa[5], pp0, v2.y);
            fma2(Aa[6], pp0, v3.x); fma2(Aa[7], pp0, v3.y);
            fma2(Ab[0], pp1, v0.x); fma2(Ab[1], pp1, v0.y);
            fma2(Ab[2], pp1, v1.x); fma2(Ab[3], pp1, v1.y);
            fma2(Ab[4], pp1, v2.x); fma2(Ab[5], pp1, v2.y);
            fma2(Ab[6], pp1, v3.x); fma2(Ab[7], pp1, v3.y);
        }
        __syncthreads();
        buf ^= 1;
    }

#pragma unroll
    for (int m = 8; m <= 16; m <<= 1) {
        S0  += __shfl_xor_sync(0xffffffffu, S0,  m);
        SQ0 += __shfl_xor_sync(0xffffffffu, SQ0, m);
        S1  += __shfl_xor_sync(0xffffffffu, S1,  m);
        SQ1 += __shfl_xor_sync(0xffffffffu, SQ1, m);
#pragma unroll
        for (int e = 0; e < 8; e++) {
            u64 v;
            v = __shfl_xor_sync(0xffffffffu, Aa[e], m); add2(Aa[e], v);
            v = __shfl_xor_sync(0xffffffffu, Ab[e], m); add2(Ab[e], v);
        }
    }

    if (ksub == 0) {
        const float i0 = 1.0f / S0, i1 = 1.0f / S1;
        const float sc0 = sqrtf(SQ0) * i0 * i0;
        const float sc1 = sqrtf(SQ1) * i1 * i1;
        float* o0 = g_out_i + (size_t)(b * Nn + q0) * DIN + (hbase + h) * 16;
        float* o1 = o0 + DIN;
#pragma unroll
        for (int e4 = 0; e4 < 4; e4++) {
            const float2 lo0 = unpack2(Aa[e4 * 2]);
            const float2 hi0 = unpack2(Aa[e4 * 2 + 1]);
            const float2 lo1 = unpack2(Ab[e4 * 2]);
            const float2 hi1 = unpack2(Ab[e4 * 2 + 1]);
            float4 v0, v1;
            v0.x = lo0.x * sc0; v0.y = lo0.y * sc0;
            v0.z = hi0.x * sc0; v0.w = hi0.y * sc0;
            v1.x = lo1.x * sc1; v1.y = lo1.y * sc1;
            v1.z = hi1.x * sc1; v1.w = hi1.y * sc1;
            *(float4*)&o0[e4 * 4] = v0;
            *(float4*)&o1[e4 * 4] = v1;
        }
    }
}

// ---------------------------------------------------------------------------
// Output kernel (inv only): 128 CTAs, 32 m-tiles x 4 n-tiles
// ---------------------------------------------------------------------------
__global__ void __launch_bounds__(256) out_kernel(
    const float* __restrict__ W_out, const float* __restrict__ b_out,
    float* __restrict__ out)
{
    __shared__ __align__(16) float sm[2 * 2 * 16 * 68];
    const int id = blockIdx.x;
    gemm_tile64(g_out_i, W_out, b_out, out + (size_t)Bsz * Nn * 3 * CEQ,
                DIN, DIN, (id >> 2) * 64, (id & 3) * 64, sm);
}

// ---------------------------------------------------------------------------
// Launch: two-stream fork/join (graph-capturable pattern).
// ---------------------------------------------------------------------------
extern "C" void kernel_launch(void* const* d_in, const int* in_sizes, int n_in,
                              void* d_out, int out_size) {
    const float* v_equi     = (const float*)d_in[0];
    const float* v_inv      = (const float*)d_in[1];
    const float* em         = (const float*)d_in[2];
    const float* im         = (const float*)d_in[3];
    const int*   adj        = (const int*)  d_in[4];
    const float* W_coord    = (const float*)d_in[5];
    const float* W_equi_out = (const float*)d_in[6];
    const float* b_equi_out = (const float*)d_in[7];
    const float* W_in       = (const float*)d_in[8];
    const float* b_in       = (const float*)d_in[9];
    const float* W_out      = (const float*)d_in[10];
    const float* b_out      = (const float*)d_in[11];
    float* out = (float*)d_out;

    static cudaStream_t s2 = nullptr;
    static cudaEvent_t ev_fork = nullptr, ev_join = nullptr;
    if (s2 == nullptr) {
        cudaStreamCreateWithFlags(&s2, cudaStreamNonBlocking);
        cudaEventCreateWithFlags(&ev_fork, cudaEventDisableTiming);
        cudaEventCreateWithFlags(&ev_join, cudaEventDisableTiming);
    }

    // fork: s2 branches off the (capture) null stream
    cudaEventRecord(ev_fork, 0);
    cudaStreamWaitEvent(s2, ev_fork, 0);

    // stream B: inv chain
    prep_i_kernel<<<128, 256, 0, s2>>>(v_inv, W_in, b_in);
    inv_attn_kernel<<<512, 128, 0, s2>>>(im, adj);
    out_kernel<<<128, 256, 0, s2>>>(W_out, b_out, out);
    cudaEventRecord(ev_join, s2);

    // stream A (null): equi chain
    prep_e_kernel<<<96, 256>>>(v_equi, W_coord);
    equi_attn_kernel<<<512, 128>>>(em, adj, W_equi_out, b_equi_out, out);

    // join
    cudaStreamWaitEvent(0, ev_join, 0);
}